// round 14
// baseline (speedup 1.0000x reference)
#include <cuda_runtime.h>
#include <cuda_fp16.h>
#include <cstdint>

// Batch Conv1D via 1D Winograd F(2,3) on mma.sync (HMMA fp16 in / fp32 acc).
// Round 14: identical to R13 except F_STRIDE fixed 136 -> 144 (R13 crashed:
// 136B row stride made float4 LDS land on 8B boundaries -> misaligned trap).
//   z0=d0-d2, z1=d1+d2, z2=d2-d1, z3=d1-d3   (d_i = x[2t+i], per channel)
//   w0=g0, w1=(g0+g1+g2)/2, w2=(g0-g1+g2)/2, w3=g2
//   y[2t]=m0+m1+m2, y[2t+1]=m1-m2-m3
// CTA: 64 tile-pairs x 64 feats x 4 phases; 8 warps (phases {0,1}/{2,3} x 2x2
// spatial); smem 113.2KB -> 2 CTAs/SM; x fp32 cp.async 2 chunks ahead; in-smem
// transform at step top (single z buffer, hidden by peer CTA); B 3-slot ring.
// MAC total 34.4G vs 51.5G standard -> floor 239us vs 357us (512 MAC/cyc/SM cap).

namespace {

constexpr int NTILES = 511;
constexpr int NCHUNK = 8;                  // 256 ch / 32
constexpr int NTHREADS = 256;

constexpr int Z_STRIDE = 80;               // 32 fp16 (64B) + 16B pad
constexpr int Z_PHASE  = 64 * Z_STRIDE;    // 5120
constexpr int Z_BYTES  = 4 * Z_PHASE;      // 20480 (single buffer)
constexpr int B_STRIDE = 144;              // 64 fp16 (128B) + 16B pad
constexpr int B_PHASE  = 32 * B_STRIDE;    // 4608
constexpr int B_BYTES  = 4 * B_PHASE;      // 18432
constexpr int F_STRIDE = 144;              // 32 fp32 (128B) + 16B pad (16B-aligned rows!)
constexpr int F_BYTES  = 130 * F_STRIDE;   // 18720

constexpr int OFF_Z = 0;
constexpr int OFF_B = Z_BYTES;                       // 20480; 3 slots
constexpr int OFF_F = OFF_B + 3 * B_BYTES;           // 75776; 2 slots
constexpr int SMEM_TOTAL = OFF_F + 2 * F_BYTES;      // 113216 -> 2 CTAs/SM

__device__ __half g_wt[4 * 256 * 256];     // [phase][c][f] Winograd weights

// ---------------- PTX helpers ----------------

__device__ __forceinline__ uint32_t smem_u32(const void* p) {
    return (uint32_t)__cvta_generic_to_shared(p);
}
__device__ __forceinline__ void cp16(uint32_t dst, const void* src) {
    asm volatile("cp.async.cg.shared.global [%0], [%1], 16;" :: "r"(dst), "l"(src));
}
__device__ __forceinline__ void cp_commit() {
    asm volatile("cp.async.commit_group;" ::: "memory");
}
__device__ __forceinline__ void cp_wait1() {
    asm volatile("cp.async.wait_group 1;" ::: "memory");
}
__device__ __forceinline__ void cp_wait0() {
    asm volatile("cp.async.wait_group 0;" ::: "memory");
}
__device__ __forceinline__ void ldsm4(uint32_t (&r)[4], uint32_t addr) {
    asm volatile("ldmatrix.sync.aligned.m8n8.x4.shared.b16 {%0,%1,%2,%3}, [%4];"
                 : "=r"(r[0]), "=r"(r[1]), "=r"(r[2]), "=r"(r[3]) : "r"(addr));
}
__device__ __forceinline__ void ldsm4t(uint32_t (&r)[4], uint32_t addr) {
    asm volatile("ldmatrix.sync.aligned.m8n8.x4.trans.shared.b16 {%0,%1,%2,%3}, [%4];"
                 : "=r"(r[0]), "=r"(r[1]), "=r"(r[2]), "=r"(r[3]) : "r"(addr));
}
__device__ __forceinline__ void mma16816(float (&c)[4], const uint32_t (&a)[4],
                                         uint32_t b0, uint32_t b1) {
    asm volatile(
        "mma.sync.aligned.m16n8k16.row.col.f32.f16.f16.f32 "
        "{%0,%1,%2,%3}, {%4,%5,%6,%7}, {%8,%9}, {%0,%1,%2,%3};"
        : "+f"(c[0]), "+f"(c[1]), "+f"(c[2]), "+f"(c[3])
        : "r"(a[0]), "r"(a[1]), "r"(a[2]), "r"(a[3]), "r"(b0), "r"(b1));
}
__device__ __forceinline__ uint32_t pack_h2(float a, float b) {
    __half2 h = __floats2half2_rn(a, b);
    return *(uint32_t*)&h;
}

// ---------------- pre-pass: Winograd weight transform (tiny) ----------------

__global__ void wgconv_kernel(const float* __restrict__ W) {
    int idx = blockIdx.x * 256 + threadIdx.x;   // 65536 = (c,f)
    float g0 = W[idx];
    float g1 = W[65536 + idx];
    float g2 = W[131072 + idx];
    g_wt[idx]          = __float2half_rn(g0);
    g_wt[65536 + idx]  = __float2half_rn(0.5f * (g0 + g1 + g2));
    g_wt[131072 + idx] = __float2half_rn(0.5f * (g0 - g1 + g2));
    g_wt[196608 + idx] = __float2half_rn(g2);
}

// ---------------- main fused Winograd kernel ----------------

__global__ __launch_bounds__(NTHREADS, 2)
void conv1d_wino_kernel(const float* __restrict__ x,
                        const float* __restrict__ bias,
                        float* __restrict__ out)
{
    extern __shared__ __align__(128) uint8_t smem[];
    const uint32_t sm = smem_u32(smem);

    const int tid  = threadIdx.x;
    const int wid  = tid >> 5;
    const int lane = tid & 31;

    const int f0  = blockIdx.x * 64;          // feature tile (4)
    const int t0  = blockIdx.y * 64;          // tile-pair block (8)
    const int img = blockIdx.z;

    const float* xb = x   + (size_t)img * (1024 * 256);
    float*       ob = out + (size_t)img * (1022 * 256);

    // warps 0-3: phases {0,1}; warps 4-7: phases {2,3}; 2x2 spatial each
    const int phb = (wid >> 2) * 2;
    const int wq  = wid & 3;
    const int wm  = (wq >> 1) * 32;            // tiles within 64
    const int wn  = (wq & 1) * 32;             // feats within 64

    const uint32_t a_lane = (uint32_t)(wm + (lane & 15)) * Z_STRIDE + (lane >> 4) * 16;
    const uint32_t b_lane = (uint32_t)(lane & 15) * B_STRIDE
                          + (uint32_t)(wn + (lane >> 4) * 8) * 2;

    // ---- stage chunk s: x fp32 (130 rows x 32 ch) + B (4ph x 32k x 64f) ----
    auto stage = [&](int s) {
        // x: 260 half-rows (64B each = 16 fp32)
        #pragma unroll
        for (int rep = 0; rep < 2; ++rep) {
            const int item = tid + rep * 256;
            if (rep == 0 || tid < 4) {
                const int row = item >> 1, seg = item & 1;
                int xr = 2 * t0 + row;
                if (xr > 1023) xr = 1023;       // clamped rows feed only tile 511 (guarded)
                const float* src = xb + (size_t)xr * 256 + s * 32 + seg * 16;
                const uint32_t d = sm + OFF_F + (s & 1) * F_BYTES
                                 + (uint32_t)row * F_STRIDE + seg * 64;
                cp16(d,      src);
                cp16(d + 16, src + 4);
                cp16(d + 32, src + 8);
                cp16(d + 48, src + 12);
            }
        }
        // B: 128 rows (4 phases x 32 k), 2 threads/row (64B each)
        {
            const int br = tid >> 1, bh = tid & 1;
            const int bp = br >> 5, bk = br & 31;
            const __half* src = g_wt + ((size_t)bp * 256 + s * 32 + bk) * 256 + f0 + bh * 32;
            const uint32_t d = sm + OFF_B + (s % 3) * B_BYTES
                             + (uint32_t)bp * B_PHASE + (uint32_t)bk * B_STRIDE + bh * 64;
            cp16(d,      src);
            cp16(d + 16, src + 8);
            cp16(d + 32, src + 16);
            cp16(d + 48, src + 24);
        }
    };

    // ---- transform: x fp32 slot (s&1) -> z fp16 (4 phases, single buffer) ----
    auto convert = [&](int s) {
        const float* xs = (const float*)(smem + OFF_F + (s & 1) * F_BYTES);
        const int ti = tid >> 2;                // tile 0..63
        const int cg = (tid & 3) * 8;           // channel group
        float4 d[4][2];
        #pragma unroll
        for (int k = 0; k < 4; ++k) {
            const float* r = xs + (size_t)(2 * ti + k) * 36 + cg;   // 36 fp32 = 144B
            d[k][0] = *(const float4*)(r);
            d[k][1] = *(const float4*)(r + 4);
        }
        uint8_t* zb = smem + OFF_Z + (uint32_t)ti * Z_STRIDE + cg * 2;
        #pragma unroll
        for (int half = 0; half < 2; ++half) {
            const float* d0 = (const float*)&d[0][half];
            const float* d1 = (const float*)&d[1][half];
            const float* d2 = (const float*)&d[2][half];
            const float* d3 = (const float*)&d[3][half];
            uint2 z0, z1, z2, z3;
            z0.x = pack_h2(d0[0] - d2[0], d0[1] - d2[1]);
            z0.y = pack_h2(d0[2] - d2[2], d0[3] - d2[3]);
            z1.x = pack_h2(d1[0] + d2[0], d1[1] + d2[1]);
            z1.y = pack_h2(d1[2] + d2[2], d1[3] + d2[3]);
            z2.x = pack_h2(d2[0] - d1[0], d2[1] - d1[1]);
            z2.y = pack_h2(d2[2] - d1[2], d2[3] - d1[3]);
            z3.x = pack_h2(d1[0] - d3[0], d1[1] - d3[1]);
            z3.y = pack_h2(d1[2] - d3[2], d1[3] - d3[3]);
            *(uint2*)(zb + 0 * Z_PHASE + half * 8) = z0;
            *(uint2*)(zb + 1 * Z_PHASE + half * 8) = z1;
            *(uint2*)(zb + 2 * Z_PHASE + half * 8) = z2;
            *(uint2*)(zb + 3 * Z_PHASE + half * 8) = z3;
        }
    };

    float acc[2][2][4][4];
    #pragma unroll
    for (int pp = 0; pp < 2; ++pp)
        #pragma unroll
        for (int mt = 0; mt < 2; ++mt)
            #pragma unroll
            for (int nt = 0; nt < 4; ++nt)
                #pragma unroll
                for (int q = 0; q < 4; ++q)
                    acc[pp][mt][nt][q] = 0.f;

    // ---- prologue: G0={x0,B0}, G1={x1,B1} ----
    stage(0);
    cp_commit();
    stage(1);
    cp_commit();
    cp_wait0();
    __syncthreads();

    for (int s = 0; s < NCHUNK; ++s) {
        // transform this chunk's z at step top (peer CTA's MMAs hide it)
        convert(s);
        __syncthreads();

        // stage 2 chunks ahead; always commit one group per step (accounting)
        if (s + 2 < NCHUNK) stage(s + 2);
        cp_commit();

        // MMA block: 2 phases per warp, z single-buffer, B slot s%3
        const uint32_t Bb = sm + OFF_B + (s % 3) * B_BYTES;
        #pragma unroll
        for (int pp = 0; pp < 2; ++pp) {
            const int p = phb + pp;
            const uint32_t Ap = sm + OFF_Z + p * Z_PHASE;
            const uint32_t Bp = Bb + p * B_PHASE;
            #pragma unroll
            for (int ks = 0; ks < 2; ++ks) {
                uint32_t af[2][4];
                ldsm4(af[0], Ap + a_lane + ks * 32);
                ldsm4(af[1], Ap + a_lane + 16 * Z_STRIDE + ks * 32);
                uint32_t bf[2][4];
                #pragma unroll
                for (int n2 = 0; n2 < 2; ++n2)
                    ldsm4t(bf[n2], Bp + b_lane + ks * (16 * B_STRIDE) + n2 * 32);
                #pragma unroll
                for (int mt = 0; mt < 2; ++mt)
                    #pragma unroll
                    for (int n2 = 0; n2 < 2; ++n2) {
                        mma16816(acc[pp][mt][2 * n2],     af[mt], bf[n2][0], bf[n2][1]);
                        mma16816(acc[pp][mt][2 * n2 + 1], af[mt], bf[n2][2], bf[n2][3]);
                    }
            }
        }

        // end of step s: G(s+1) complete -> x(s+1) for next convert, B(s+1)
        if (s + 1 < NCHUNK) cp_wait1();
        __syncthreads();
    }

    // ---- epilogue: warps 4-7 ship m2,m3 via smem; warps 0-3 combine+store ----
    if (wid >= 4) {
        uint8_t* ex = smem + (size_t)(wid - 4) * 8192;
        #pragma unroll
        for (int pp = 0; pp < 2; ++pp)
            #pragma unroll
            for (int mt = 0; mt < 2; ++mt)
                #pragma unroll
                for (int nt = 0; nt < 4; ++nt)
                    *(float4*)(ex + (((pp * 2 + mt) * 4 + nt) * 512) + lane * 16)
                        = *(const float4*)&acc[pp][mt][nt][0];
    }
    __syncthreads();

    if (wid < 4) {
        const uint8_t* ex = smem + (size_t)wq * 8192;
        const int g  = lane >> 2;
        const int tq = lane & 3;
        #pragma unroll
        for (int nt = 0; nt < 4; ++nt) {
            const int col = f0 + wn + nt * 8 + tq * 2;
            const float b0 = __ldg(bias + col);
            const float b1 = __ldg(bias + col + 1);
            #pragma unroll
            for (int mt = 0; mt < 2; ++mt) {
                float4 m2 = *(const float4*)(ex + (((0 * 2 + mt) * 4 + nt) * 512) + lane * 16);
                float4 m3 = *(const float4*)(ex + (((1 * 2 + mt) * 4 + nt) * 512) + lane * 16);
                const float* m0 = acc[0][mt][nt];
                const float* m1 = acc[1][mt][nt];
                const int r = t0 + wm + mt * 16 + g;      // tile-pair index
                if (r < NTILES) {
                    float y00 = m0[0] + m1[0] + m2.x + b0;
                    float y01 = m0[1] + m1[1] + m2.y + b1;
                    float y10 = m1[0] - m2.x - m3.x + b0;
                    float y11 = m1[1] - m2.y - m3.y + b1;
                    *(float2*)(ob + (size_t)(2 * r) * 256 + col)     = make_float2(y00, y01);
                    *(float2*)(ob + (size_t)(2 * r + 1) * 256 + col) = make_float2(y10, y11);
                }
                const int r2 = r + 8;
                if (r2 < NTILES) {
                    float y00 = m0[2] + m1[2] + m2.z + b0;
                    float y01 = m0[3] + m1[3] + m2.w + b1;
                    float y10 = m1[2] - m2.z - m3.z + b0;
                    float y11 = m1[3] - m2.w - m3.w + b1;
                    *(float2*)(ob + (size_t)(2 * r2) * 256 + col)     = make_float2(y00, y01);
                    *(float2*)(ob + (size_t)(2 * r2 + 1) * 256 + col) = make_float2(y10, y11);
                }
            }
        }
    }
}

}  // namespace

extern "C" void kernel_launch(void* const* d_in, const int* in_sizes, int n_in,
                              void* d_out, int out_size)
{
    const float* x  = (const float*)d_in[0];   // [8,32,1024,256]
    const float* w  = (const float*)d_in[1];   // [3,256,256]
    const float* b  = (const float*)d_in[2];   // [256]
    float* out      = (float*)d_out;           // [8,32,1022,256]

    wgconv_kernel<<<256, 256>>>(w);            // Winograd weight transform

    cudaFuncSetAttribute(conv1d_wino_kernel,
                         cudaFuncAttributeMaxDynamicSharedMemorySize, SMEM_TOTAL);

    dim3 grid(4, 8, 256);                      // f-tiles, tile-blocks, images
    conv1d_wino_kernel<<<grid, NTHREADS, SMEM_TOTAL>>>(x, b, out);
}